// round 6
// baseline (speedup 1.0000x reference)
#include <cuda_runtime.h>
#include <cuda_bf16.h>

#define FULLMASK 0xffffffffu
#define TT 4096
#define NB 128          // blocks (<= SM count -> guaranteed co-resident)
#define NW 16           // warps per block (1 row per warp)

// ---- device scratch (allocation-free, zero-init) ----
__device__ volatile unsigned g_bar_count[3];
__device__ volatile unsigned g_bar_flag[3];
__device__ float g_p0[NB][64];   // per-block feature col sum[32] + sumsq[32]
__device__ float g_p1[NB][16];   // per-block h1 sum[8] + sumsq[8]
__device__ float g_p2[NB][16];   // per-block h2 sum[8] + sumsq[8]

// Replay-safe grid barrier. Slot s is used; slot (s+1)%3 is reset by the last
// arriver BEFORE release, so each slot is clean before its next use — across
// an arbitrary number of graph replays (first launch relies on zero-init).
__device__ __forceinline__ void grid_barrier(int s) {
    __syncthreads();
    if (threadIdx.x == 0) {
        __threadfence();
        unsigned old = atomicAdd((unsigned*)&g_bar_count[s], 1u);
        if (old == NB - 1) {
            int r = (s + 1) % 3;
            g_bar_count[r] = 0u;
            g_bar_flag[r] = 0u;
            __threadfence();
            g_bar_flag[s] = 1u;
        } else {
            while (g_bar_flag[s] == 0u) __nanosleep(32);
        }
        __threadfence();
    }
    __syncthreads();
}

__global__ __launch_bounds__(512, 1) void fused_all(
    const float* __restrict__ X,
    const float* __restrict__ features,
    const float* __restrict__ Fp,
    const float* __restrict__ bn0_g, const float* __restrict__ bn0_b,
    const float* __restrict__ W1,    const float* __restrict__ b1,
    const float* __restrict__ bn1_g, const float* __restrict__ bn1_b,
    const float* __restrict__ W2,    const float* __restrict__ b2,
    const float* __restrict__ bn2_g, const float* __restrict__ bn2_b,
    const float* __restrict__ W3,    const float* __restrict__ b3,
    const float* __restrict__ pn,
    float* __restrict__ out)
{
    __shared__ float s_sum[NW][32], s_sq[NW][32];
    __shared__ float s_acc[8][64];
    __shared__ float s_acc2[32][16];
    __shared__ float s_p[NW][16];
    __shared__ float sW1[256], sW2[64], sW3[48];
    __shared__ float sb1[8], sb2[8], sb3[6], spn[6];
    __shared__ float s_sc0[32], s_sh0[32];
    __shared__ float s_sc1[8], s_sh1[8];
    __shared__ float s_sc2[8], s_sh2[8];

    const int tid  = threadIdx.x;
    const int warp = tid >> 5;
    const int lane = tid & 31;
    const int row  = blockIdx.x * NW + warp;   // 0..2047

    // ---------- P0: feature load (coalesced: lane = column), bn0 partials ----------
    const float fv = features[(size_t)row * 32 + lane];
    s_sum[warp][lane] = fv;
    s_sq [warp][lane] = fv * fv;
    // stage weights while we're at it
    if (tid < 256) sW1[tid] = W1[tid];
    else if (tid < 320) sW2[tid - 256] = W2[tid - 256];
    else if (tid < 368) sW3[tid - 320] = W3[tid - 320];
    else if (tid < 376) sb1[tid - 368] = b1[tid - 368];
    else if (tid < 384) sb2[tid - 376] = b2[tid - 376];
    else if (tid < 390) sb3[tid - 384] = b3[tid - 384];
    else if (tid < 396) spn[tid - 390] = pn[tid - 390];
    __syncthreads();
    if (tid < 64) {
        float a = 0.f;
        const int half = tid >> 5, col = tid & 31;
        #pragma unroll
        for (int w = 0; w < NW; w++) a += half ? s_sq[w][col] : s_sum[w][col];
        g_p0[blockIdx.x][tid] = a;
    }
    grid_barrier(0);

    // ---------- P1: finalize bn0, h1 = bn0(f) @ W1^T + b1, bn1 partials ----------
    {
        const int col = tid & 63, ch = tid >> 6;    // 8 chunks of 16 blocks
        float a = 0.f;
        #pragma unroll
        for (int b = 0; b < 16; b++) a += g_p0[ch * 16 + b][col];
        s_acc[ch][col] = a;
    }
    __syncthreads();
    if (tid < 32) {
        float ss = 0.f, qq = 0.f;
        #pragma unroll
        for (int c = 0; c < 8; c++) { ss += s_acc[c][tid]; qq += s_acc[c][32 + tid]; }
        float mean = ss * (1.f / 2048.f);
        float var  = qq * (1.f / 2048.f) - mean * mean;
        float sc   = bn0_g[tid] * rsqrtf(var + 1e-5f);
        s_sc0[tid] = sc;
        s_sh0[tid] = bn0_b[tid] - mean * sc;
    }
    __syncthreads();

    const float xn = fmaf(fv, s_sc0[lane], s_sh0[lane]);
    float h[8];
    #pragma unroll
    for (int j = 0; j < 8; j++) {
        float a = sW1[j * 32 + lane] * xn;
        #pragma unroll
        for (int d = 16; d; d >>= 1) a += __shfl_xor_sync(FULLMASK, a, d);
        h[j] = a + sb1[j];            // all lanes hold h1_j
    }
    if (lane < 16) s_p[warp][lane] = (lane < 8) ? h[lane] : h[lane - 8] * h[lane - 8];
    __syncthreads();
    if (tid < 16) {
        float a = 0.f;
        #pragma unroll
        for (int w = 0; w < NW; w++) a += s_p[w][tid];
        g_p1[blockIdx.x][tid] = a;
    }
    grid_barrier(1);

    // ---------- P2: finalize bn1, h2 = relu(bn1(h1)) @ W2^T + b2, bn2 partials ----------
    {
        const int v = tid & 15, ch = tid >> 4;      // 32 chunks of 4 blocks
        float a = 0.f;
        #pragma unroll
        for (int b = 0; b < 4; b++) a += g_p1[ch * 4 + b][v];
        s_acc2[ch][v] = a;
    }
    __syncthreads();
    if (tid < 8) {
        float ss = 0.f, qq = 0.f;
        #pragma unroll
        for (int c = 0; c < 32; c++) { ss += s_acc2[c][tid]; qq += s_acc2[c][8 + tid]; }
        float mean = ss * (1.f / 2048.f);
        float var  = qq * (1.f / 2048.f) - mean * mean;
        float sc   = bn1_g[tid] * rsqrtf(var + 1e-5f);
        s_sc1[tid] = sc;
        s_sh1[tid] = bn1_b[tid] - mean * sc;
    }
    __syncthreads();

    float z[8];
    #pragma unroll
    for (int j = 0; j < 8; j++) z[j] = fmaxf(fmaf(h[j], s_sc1[j], s_sh1[j]), 0.f);
    #pragma unroll
    for (int k = 0; k < 8; k++) {
        float a = sb2[k];
        #pragma unroll
        for (int j = 0; j < 8; j++) a = fmaf(sW2[k * 8 + j], z[j], a);
        h[k] = a;                     // h now holds h2 (all lanes)
    }
    __syncthreads();                  // s_p reuse
    if (lane < 16) s_p[warp][lane] = (lane < 8) ? h[lane] : h[lane - 8] * h[lane - 8];
    __syncthreads();
    if (tid < 16) {
        float a = 0.f;
        #pragma unroll
        for (int w = 0; w < NW; w++) a += s_p[w][tid];
        g_p2[blockIdx.x][tid] = a;
    }
    grid_barrier(2);

    // ---------- P3: finalize bn2, corr -> sigmoids -> per-row scan params ----------
    {
        const int v = tid & 15, ch = tid >> 4;
        float a = 0.f;
        #pragma unroll
        for (int b = 0; b < 4; b++) a += g_p2[ch * 4 + b][v];
        s_acc2[ch][v] = a;
    }
    __syncthreads();
    if (tid < 8) {
        float ss = 0.f, qq = 0.f;
        #pragma unroll
        for (int c = 0; c < 32; c++) { ss += s_acc2[c][tid]; qq += s_acc2[c][8 + tid]; }
        float mean = ss * (1.f / 2048.f);
        float var  = qq * (1.f / 2048.f) - mean * mean;
        float sc   = bn2_g[tid] * rsqrtf(var + 1e-5f);
        s_sc2[tid] = sc;
        s_sh2[tid] = bn2_b[tid] - mean * sc;
    }
    __syncthreads();

    #pragma unroll
    for (int j = 0; j < 8; j++) z[j] = fmaxf(fmaf(h[j], s_sc2[j], s_sh2[j]), 0.f);
    float sg[6];
    #pragma unroll
    for (int j = 0; j < 6; j++) {
        float a = sb3[j] + spn[j];
        #pragma unroll
        for (int k = 0; k < 8; k++) a = fmaf(sW3[j * 8 + k], z[k], a);
        sg[j] = __fdividef(1.f, 1.f + __expf(-a));
    }
    const float f_start = fmaf(4.5f,  sg[0], 0.5f);
    const float f_inf   = fmaf(0.49f, sg[1], 0.01f);
    const float f_decay = 2.f * sg[2];
    const float f_T     = 2.f * sg[3];
    const float w_off   = sg[4];
    const float w_T     = fmaf(0.49f, sg[5], 0.01f);

    const float df  = f_start - f_inf;
    const float lnD = fmaf(-2.30258509f, f_decay, -0.35667494f);  // ln(0.7*0.1^fd)
    const float H   = 10.f * __expf(-2.30258509f * f_T);          // 10*0.1^fT
    const float kf  = __fdividef(lnD, 4096.f * H);
    const float G   = __expf(kf);
    const float z0  = __fdividef(w_off, w_T);
    const float lw  = -__fdividef(1.f, 4096.f * w_T);
    const float R   = __expf(lw);
    const float cc  = 0.16228221f * __ldg(Fp);   // sqrt(2^(1/3)-1)*F/pi

    // ---------- P4: affine-chunked IIR scan + weighted average ----------
    // Lane l scans steps [128l,128l+128) in closed affine form
    // (transform [[p,0],[r,p]] + offset (q1,q2)); output accumulators
    // (a1,a2,bt,ws) are affine in the chunk's entry state.
    const float* xrow = X + (size_t)row * TT;
    const int t0 = lane << 7;
    float g = __expf(kf * (float)t0);
    float e = __expf(fmaf(lw, (float)t0, z0));  // may be inf -> w = 0 (correct)
    float xp = __ldcs(xrow + (t0 ? t0 - 1 : 0));

    float p = 1.f, r = 0.f, q1 = 0.f, q2 = 0.f;
    float a1 = 0.f, a2 = 0.f, bt = 0.f, ws = 0.f;

    const float4* xv = (const float4*)(xrow + t0);
    float4 v = __ldcs(xv);
    const float y0 = __shfl_sync(FULLMASK, v.x, 0);

#define STEP(xval) do {                               \
    float w_ = __fdividef(1.f, 1.f + e);              \
    float f_ = fmaf(df, g, f_inf);                    \
    float ap = __fdividef(cc - f_, cc + f_);          \
    g *= G; e *= R;                                   \
    float b_ = fmaf(-0.5f, ap, 0.5f);                 \
    float m_ = fmaf(b_, ap, b_);                      \
    float xx = (xval) + xp;                           \
    float u1 = b_ * xx;                               \
    float u2 = b_ * u1;                               \
    float pm = m_ * p;                                \
    float t2 = fmaf(m_, q1, u2);                      \
    p = ap * p;                                       \
    r = fmaf(ap, r, pm);                              \
    q1 = fmaf(ap, q1, u1);                            \
    q2 = fmaf(ap, q2, t2);                            \
    a1 = fmaf(w_, r, a1);                             \
    a2 = fmaf(w_, p, a2);                             \
    bt = fmaf(w_, q2, bt);                            \
    ws += w_;                                         \
    xp = (xval);                                      \
  } while (0)

    if (lane == 0) {
        // t = 0: y2_0 = y0 passes through identity -> a2 += w0, ws += w0
        float w0 = __fdividef(1.f, 1.f + e);
        a2 = w0; ws = w0;
        g *= G; e *= R;
        // xp stays X[0] for the t=1 step
    } else {
        STEP(v.x);
    }
    STEP(v.y); STEP(v.z); STEP(v.w);
    #pragma unroll 2
    for (int i = 1; i < 32; i++) {
        v = __ldcs(xv + i);
        STEP(v.x); STEP(v.y); STEP(v.z); STEP(v.w);
    }
#undef STEP

    // inclusive scan: compose self with prefix from lower lanes
    #pragma unroll
    for (int d = 1; d < 32; d <<= 1) {
        float pL  = __shfl_up_sync(FULLMASK, p,  d);
        float rL  = __shfl_up_sync(FULLMASK, r,  d);
        float q1L = __shfl_up_sync(FULLMASK, q1, d);
        float q2L = __shfl_up_sync(FULLMASK, q2, d);
        if (lane >= d) {
            float pn2 = p * pL;
            float rn  = fmaf(r, pL, p * rL);
            float q1n = fmaf(p, q1L, q1);
            float q2n = fmaf(r, q1L, fmaf(p, q2L, q2));
            p = pn2; r = rn; q1 = q1n; q2 = q2n;
        }
    }
    // exclusive shift (identity into lane 0)
    float pe  = __shfl_up_sync(FULLMASK, p,  1);
    float re  = __shfl_up_sync(FULLMASK, r,  1);
    float q1e = __shfl_up_sync(FULLMASK, q1, 1);
    float q2e = __shfl_up_sync(FULLMASK, q2, 1);
    if (lane == 0) { pe = 1.f; re = 0.f; q1e = 0.f; q2e = 0.f; }

    const float y1i = fmaf(pe, y0, q1e);
    const float y2i = fmaf(re + pe, y0, q2e);
    float contrib = fmaf(a1, y1i, fmaf(a2, y2i, bt));

    #pragma unroll
    for (int d = 16; d; d >>= 1) {
        contrib += __shfl_xor_sync(FULLMASK, contrib, d);
        ws      += __shfl_xor_sync(FULLMASK, ws, d);
    }
    if (lane == 0) out[row] = contrib / ws;
}

extern "C" void kernel_launch(void* const* d_in, const int* in_sizes, int n_in,
                              void* d_out, int out_size) {
    const float* X        = (const float*)d_in[0];
    const float* features = (const float*)d_in[1];
    const float* F        = (const float*)d_in[2];
    const float* bn0_g    = (const float*)d_in[3];
    const float* bn0_b    = (const float*)d_in[4];
    const float* W1       = (const float*)d_in[5];
    const float* b1       = (const float*)d_in[6];
    const float* bn1_g    = (const float*)d_in[7];
    const float* bn1_b    = (const float*)d_in[8];
    const float* W2       = (const float*)d_in[9];
    const float* b2       = (const float*)d_in[10];
    const float* bn2_g    = (const float*)d_in[11];
    const float* bn2_b    = (const float*)d_in[12];
    const float* W3       = (const float*)d_in[13];
    const float* b3       = (const float*)d_in[14];
    const float* pn       = (const float*)d_in[15];
    float* out = (float*)d_out;

    fused_all<<<NB, 512>>>(X, features, F, bn0_g, bn0_b, W1, b1,
                           bn1_g, bn1_b, W2, b2, bn2_g, bn2_b, W3, b3, pn, out);
}